// round 1
// baseline (speedup 1.0000x reference)
#include <cuda_runtime.h>
#include <math.h>

#define NN 50000
#define EE 800000
#define HH 128
#define CC 10
#define GG 128
#define NHID 3

// ---------------- device scratch (static, no allocation) ----------------
__device__ int   g_outdeg[NN];
__device__ int   g_indeg[NN];
__device__ float g_csrc[NN];
__device__ float g_cdst[NN];
__device__ int   g_rowptr[NN + 1];
__device__ int   g_fill[NN];
__device__ int   g_col[EE];
__device__ float g_m[NN * HH];
__device__ float g_h1[NN * HH];
__device__ float g_h2[NN * HH];
__device__ float g_hg[GG * HH];
__device__ int   g_cnt[GG];

// ---------------- kernels ----------------

__global__ void zero_kernel() {
    int i = blockIdx.x * blockDim.x + threadIdx.x;
    if (i < NN) { g_outdeg[i] = 0; g_indeg[i] = 0; }
    if (i < GG * HH) g_hg[i] = 0.0f;
    if (i < GG) g_cnt[i] = 0;
}

__global__ void degree_kernel(const int* __restrict__ ei) {
    int e = blockIdx.x * blockDim.x + threadIdx.x;
    if (e >= EE) return;
    atomicAdd(&g_outdeg[ei[e]], 1);        // src row
    atomicAdd(&g_indeg[ei[EE + e]], 1);    // dst row
}

__global__ void norm_kernel() {
    int i = blockIdx.x * blockDim.x + threadIdx.x;
    if (i >= NN) return;
    float od = (float)g_outdeg[i];
    float id = (float)g_indeg[i];
    g_csrc[i] = rsqrtf(fmaxf(od, 1.0f));
    g_cdst[i] = rsqrtf(fmaxf(id, 1.0f));
}

// single-block exclusive scan over in-degrees -> rowptr (+ fill counters)
__global__ void scan_kernel() {
    __shared__ int ssum[1024];
    const int t = threadIdx.x;
    const int CH = (NN + 1023) / 1024;   // 49
    int begin = t * CH;
    int end = begin + CH; if (end > NN) end = NN;
    if (begin > NN) begin = NN;
    int s = 0;
    for (int i = begin; i < end; i++) s += g_indeg[i];
    ssum[t] = s;
    __syncthreads();
    // Hillis-Steele inclusive scan
    for (int off = 1; off < 1024; off <<= 1) {
        int v = (t >= off) ? ssum[t - off] : 0;
        __syncthreads();
        ssum[t] += v;
        __syncthreads();
    }
    int run = (t == 0) ? 0 : ssum[t - 1];  // exclusive prefix of this chunk
    for (int i = begin; i < end; i++) {
        g_rowptr[i] = run;
        g_fill[i]   = run;
        run += g_indeg[i];
    }
    if (t == 0) g_rowptr[NN] = ssum[1023];
}

__global__ void csr_fill_kernel(const int* __restrict__ ei) {
    int e = blockIdx.x * blockDim.x + threadIdx.x;
    if (e >= EE) return;
    int d = ei[EE + e];
    int pos = atomicAdd(&g_fill[d], 1);
    g_col[pos] = ei[e];
}

// one warp per destination row: m[d] = c_dst[d] * sum_{s in N(d)} c_src[s] * h[s]
__global__ void spmm_kernel(const float* __restrict__ hin, float* __restrict__ mout) {
    int gw = (blockIdx.x * blockDim.x + threadIdx.x) >> 5;
    int lane = threadIdx.x & 31;
    if (gw >= NN) return;
    int e0 = g_rowptr[gw];
    int e1 = g_rowptr[gw + 1];
    const float4* h4 = (const float4*)hin;
    float4 acc = make_float4(0.f, 0.f, 0.f, 0.f);
    for (int e = e0; e < e1; e++) {
        int s = g_col[e];
        float cs = g_csrc[s];
        float4 v = h4[s * 32 + lane];
        acc.x = fmaf(cs, v.x, acc.x);
        acc.y = fmaf(cs, v.y, acc.y);
        acc.z = fmaf(cs, v.z, acc.z);
        acc.w = fmaf(cs, v.w, acc.w);
    }
    float cd = g_cdst[gw];
    float4 o = make_float4(acc.x * cd, acc.y * cd, acc.z * cd, acc.w * cd);
    ((float4*)mout)[gw * 32 + lane] = o;
}

// out[r] = relu(A[r] @ W + b)   A: [NN,128], W: [128,128], out: [NN,128]
// block: 256 threads, 64-row tile. W fully in smem, A tile in smem.
__global__ __launch_bounds__(256) void gemm_relu_kernel(
    const float* __restrict__ A, const float* __restrict__ W,
    const float* __restrict__ bias, float* __restrict__ out) {
    extern __shared__ float sm[];
    float* sW = sm;              // 128*128
    float* sA = sm + 128 * 128;  // 64*128
    const int t = threadIdx.x;
    const int row0 = blockIdx.x * 64;

    const float4* W4 = (const float4*)W;
    float4* sW4 = (float4*)sW;
    #pragma unroll
    for (int i = t; i < 128 * 32; i += 256) sW4[i] = W4[i];

    const float4* A4 = (const float4*)A;
    float4* sA4 = (float4*)sA;
    #pragma unroll
    for (int i = t; i < 64 * 32; i += 256) {
        int r = row0 + (i >> 5);
        sA4[i] = (r < NN) ? A4[r * 32 + (i & 31)] : make_float4(0.f, 0.f, 0.f, 0.f);
    }
    __syncthreads();

    const int tx = t & 31;   // output col group (4 cols)
    const int ty = t >> 5;   // row group (8 rows)
    float4 acc[8];
    #pragma unroll
    for (int j = 0; j < 8; j++) acc[j] = make_float4(0.f, 0.f, 0.f, 0.f);

    #pragma unroll 4
    for (int k = 0; k < 128; k++) {
        float4 w = sW4[k * 32 + tx];
        #pragma unroll
        for (int j = 0; j < 8; j++) {
            float a = sA[(ty * 8 + j) * 128 + k];
            acc[j].x = fmaf(a, w.x, acc[j].x);
            acc[j].y = fmaf(a, w.y, acc[j].y);
            acc[j].z = fmaf(a, w.z, acc[j].z);
            acc[j].w = fmaf(a, w.w, acc[j].w);
        }
    }

    float4 bv = ((const float4*)bias)[tx];
    float4* out4 = (float4*)out;
    #pragma unroll
    for (int j = 0; j < 8; j++) {
        int r = row0 + ty * 8 + j;
        if (r < NN) {
            float4 o;
            o.x = fmaxf(acc[j].x + bv.x, 0.f);
            o.y = fmaxf(acc[j].y + bv.y, 0.f);
            o.z = fmaxf(acc[j].z + bv.z, 0.f);
            o.w = fmaxf(acc[j].w + bv.w, 0.f);
            out4[r * 32 + tx] = o;
        }
    }
}

// accumulate per-graph sums (sorted graph_ids, but atomics are cheap here)
__global__ void readout_kernel(const float* __restrict__ h, const int* __restrict__ gid) {
    int idx = blockIdx.x * blockDim.x + threadIdx.x;
    int n = idx >> 5, lane = idx & 31;
    if (n >= NN) return;
    int g = gid[n];
    float4 v = ((const float4*)h)[n * 32 + lane];
    float* dst = &g_hg[g * HH + lane * 4];
    atomicAdd(dst + 0, v.x);
    atomicAdd(dst + 1, v.y);
    atomicAdd(dst + 2, v.z);
    atomicAdd(dst + 3, v.w);
    if (lane == 0) atomicAdd(&g_cnt[g], 1);
}

__global__ void final_kernel(const float* __restrict__ Wc, const float* __restrict__ bc,
                             float* __restrict__ out) {
    int idx = blockIdx.x * blockDim.x + threadIdx.x;
    if (idx >= GG * CC) return;
    int g = idx / CC, c = idx % CC;
    float cnt = fmaxf((float)g_cnt[g], 1.0f);
    float inv = 1.0f / cnt;
    float sum = 0.f;
    #pragma unroll 8
    for (int k = 0; k < HH; k++) sum = fmaf(g_hg[g * HH + k], Wc[k * CC + c], sum);
    out[idx] = sum * inv + bc[c];
}

// ---------------- host launcher ----------------
extern "C" void kernel_launch(void* const* d_in, const int* in_sizes, int n_in,
                              void* d_out, int out_size) {
    const float* x   = (const float*)d_in[0];
    const float* W0  = (const float*)d_in[1];
    const float* b0  = (const float*)d_in[2];
    const float* Ws  = (const float*)d_in[3];
    const float* bs  = (const float*)d_in[4];
    const float* Wc  = (const float*)d_in[5];
    const float* bc  = (const float*)d_in[6];
    const int*   ei  = (const int*)d_in[7];
    const int*   gid = (const int*)d_in[8];
    float* out = (float*)d_out;

    float *h1, *h2, *m;
    cudaGetSymbolAddress((void**)&h1, g_h1);
    cudaGetSymbolAddress((void**)&h2, g_h2);
    cudaGetSymbolAddress((void**)&m,  g_m);

    const int GEMM_SMEM = (128 * 128 + 64 * 128) * (int)sizeof(float);  // 96KB
    cudaFuncSetAttribute(gemm_relu_kernel,
                         cudaFuncAttributeMaxDynamicSharedMemorySize, GEMM_SMEM);

    // graph preprocessing
    zero_kernel<<<(NN + 255) / 256, 256>>>();
    degree_kernel<<<(EE + 255) / 256, 256>>>(ei);
    norm_kernel<<<(NN + 255) / 256, 256>>>();
    scan_kernel<<<1, 1024>>>();
    csr_fill_kernel<<<(EE + 255) / 256, 256>>>(ei);

    const int SPMM_BLOCKS = (NN + 7) / 8;        // 8 warps/block
    const int GEMM_BLOCKS = (NN + 63) / 64;

    // layer 0
    spmm_kernel<<<SPMM_BLOCKS, 256>>>(x, m);
    gemm_relu_kernel<<<GEMM_BLOCKS, 256, GEMM_SMEM>>>(m, W0, b0, h1);
    // layer 1
    spmm_kernel<<<SPMM_BLOCKS, 256>>>(h1, m);
    gemm_relu_kernel<<<GEMM_BLOCKS, 256, GEMM_SMEM>>>(m, Ws + 0 * 128 * 128, bs + 0 * 128, h2);
    // layer 2
    spmm_kernel<<<SPMM_BLOCKS, 256>>>(h2, m);
    gemm_relu_kernel<<<GEMM_BLOCKS, 256, GEMM_SMEM>>>(m, Ws + 1 * 128 * 128, bs + 1 * 128, h1);
    // layer 3
    spmm_kernel<<<SPMM_BLOCKS, 256>>>(h1, m);
    gemm_relu_kernel<<<GEMM_BLOCKS, 256, GEMM_SMEM>>>(m, Ws + 2 * 128 * 128, bs + 2 * 128, h2);

    // readout + classifier head
    readout_kernel<<<(NN * 32 + 255) / 256, 256>>>(h2, gid);
    final_kernel<<<(GG * CC + 127) / 128, 128>>>(Wc, bc, out);
}